// round 4
// baseline (speedup 1.0000x reference)
#include <cuda_runtime.h>
#include <cuda_bf16.h>

#define EPS 1e-6f
#define RROWS 32   // output rows per thread

__device__ __forceinline__ float fast_rcp(float a) {
    float r;
    asm("rcp.approx.f32 %0, %1;" : "=f"(r) : "f"(a));
    return r;
}

__global__ __launch_bounds__(256)
void entropy2x2_lane_kernel(const float* __restrict__ x, float* __restrict__ out)
{
    const int lane  = threadIdx.x & 31;
    const int warp  = threadIdx.x >> 5;        // 8 warps -> 8 column strips of 32
    const int plane = blockIdx.z;              // 0..511
    const int c     = warp * 32 + lane;        // 0..255 (col 255 output invalid)
    const int yBase = blockIdx.y * RROWS;

    const float* __restrict__ prow = x + (size_t)plane * (256 * 256)
                                       + (size_t)yBase * 256 + c;
    float* __restrict__ po = out + (size_t)plane * (255 * 255)
                                 + (size_t)yBase * 255 + c;

    const bool storeOK = (c < 255);
    const bool edge    = (lane == 31) && (c + 1 < 256);  // lane31 patches neighbor

    // ---- prime previous row ----
    float hv_p, hl_p;
    {
        float v  = prow[0];
        float l  = v * __logf(v + EPS);
        float vn = __shfl_down_sync(0xffffffffu, v, 1);
        float ln = __shfl_down_sync(0xffffffffu, l, 1);
        if (edge) { vn = prow[1]; ln = vn * __logf(vn + EPS); }
        hv_p = v + vn;
        hl_p = l + ln;
        prow += 256;
    }

    #pragma unroll 4
    for (int r = 0; r < RROWS; r++) {
        const int gy = yBase + r;
        if (gy >= 255) break;                  // trims only the last row-block

        // load next input row (fully coalesced 128B/warp)
        float v  = prow[0];
        float l  = v * __logf(v + EPS);
        float vn = __shfl_down_sync(0xffffffffu, v, 1);
        float ln = __shfl_down_sync(0xffffffffu, l, 1);
        if (edge) { vn = prow[1]; ln = vn * __logf(vn + EPS); }
        float hv_c = v + vn;
        float hl_c = l + ln;

        // 2x2 window = prev-row pair + cur-row pair
        float s  = hv_p + hv_c;
        float sl = hl_p + hl_c;
        float S  = s + EPS;
        // ent = (s*log(S) - sum w*log(w+eps)) / S
        float ent = fmaf(s, __logf(S), -sl) * fast_rcp(S);
        if (storeOK) po[0] = ent;              // coalesced 128B/warp store

        hv_p = hv_c;
        hl_p = hl_c;
        prow += 256;
        po   += 255;
    }
}

extern "C" void kernel_launch(void* const* d_in, const int* in_sizes, int n_in,
                              void* d_out, int out_size)
{
    const float* x = (const float*)d_in[0];
    float* out = (float*)d_out;

    // 8 warps cover 256 columns; grid.y * RROWS = 256 covers 255 output rows.
    dim3 block(256);
    dim3 grid(1, 256 / RROWS, 512);
    entropy2x2_lane_kernel<<<grid, block>>>(x, out);
}

// round 5
// speedup vs baseline: 1.2474x; 1.2474x over previous
#include <cuda_runtime.h>
#include <cuda_bf16.h>

#define EPS   1e-6f
#define LN2   0.6931471805599453f
#define RROWS 51   // 255 = 5 * 51 -> uniform trip count, no in-loop break

__device__ __forceinline__ float fast_rcp(float a) {
    float r;
    asm("rcp.approx.f32 %0, %1;" : "=f"(r) : "f"(a));
    return r;
}

__global__ __launch_bounds__(256)
void entropy2x2_k4(const float* __restrict__ x, float* __restrict__ out)
{
    const int c     = threadIdx.x;             // lane-consecutive column, 0..255
    const int plane = blockIdx.z;              // 0..511
    const int yBase = blockIdx.y * RROWS;      // 0,51,102,153,204

    const float* __restrict__ p  = x   + (size_t)plane * (256 * 256)
                                       + (size_t)yBase * 256 + c;
    float*       __restrict__ po = out + (size_t)plane * (255 * 255)
                                       + (size_t)yBase * 255 + c;

    const bool ok = (c < 255);                 // col 255 produces no output

    // ---- prime previous row (row yBase) ----
    float hv_p, hl_p;
    {
        float v  = p[0];
        float vn = ok ? p[1] : 0.0f;           // predicated: avoids OOB corner
        float l  = v  * __log2f(v  + EPS);
        float ln = vn * __log2f(vn + EPS);
        hv_p = v + vn;
        hl_p = l + ln;
        p += 256;
    }

    #pragma unroll 3
    for (int r = 0; r < RROWS; r++) {
        float v  = p[0];                       // 128B coalesced
        float vn = ok ? p[1] : 0.0f;           // overlapping lines -> L1 hit
        float l  = v  * __log2f(v  + EPS);
        float ln = vn * __log2f(vn + EPS);
        float hv = v + vn;
        float hl = l + ln;

        float s   = hv_p + hv;                 // 2x2 window sum
        float sl  = hl_p + hl;                 // sum of w*lg2(w+eps)
        float S   = s + EPS;
        float inv = fast_rcp(S);
        // ent = ln2 * (s*lg2(S) - sl) / S
        float ent = fmaf(s, __log2f(S), -sl) * inv * LN2;
        if (ok) po[0] = ent;                   // 128B coalesced store

        hv_p = hv;
        hl_p = hl;
        p  += 256;
        po += 255;
    }
}

extern "C" void kernel_launch(void* const* d_in, const int* in_sizes, int n_in,
                              void* d_out, int out_size)
{
    const float* x = (const float*)d_in[0];
    float* out = (float*)d_out;

    // 256 lanes = full row of columns; 5 row-strips of 51 cover 255 output rows.
    dim3 block(256);
    dim3 grid(1, 5, 512);
    entropy2x2_k4<<<grid, block>>>(x, out);
}

// round 7
// speedup vs baseline: 1.3413x; 1.0753x over previous
#include <cuda_runtime.h>
#include <cuda_bf16.h>

#define EPS   1e-6f
#define LN2   0.6931471805599453f
#define RROWS 51   // 255 = 5 * 51 -> uniform trip count, no in-loop break
#define OUTW  31   // outputs per warp (warps overlap by 1 column)

__device__ __forceinline__ float fast_rcp(float a) {
    float r;
    asm("rcp.approx.f32 %0, %1;" : "=f"(r) : "f"(a));
    return r;
}

__global__ __launch_bounds__(288)
void entropy2x2_k5(const float* __restrict__ x, float* __restrict__ out)
{
    const int lane  = threadIdx.x & 31;
    const int warp  = threadIdx.x >> 5;        // 0..8
    const int plane = blockIdx.z;              // 0..511
    const int oc    = warp * OUTW + lane;      // output col (lane<31), 0..278
    const int lc    = min(oc, 255);            // load col, clamped (stays coalesced)
    const int yBase = blockIdx.y * RROWS;      // 0,51,102,153,204

    const float* __restrict__ p  = x   + (size_t)plane * (256 * 256)
                                       + (size_t)yBase * 256 + lc;
    float*       __restrict__ po = out + (size_t)plane * (255 * 255)
                                       + (size_t)yBase * 255 + oc;

    const bool storeOK = (lane < OUTW) && (oc < 255);

    // ---- prime previous row ----
    float hv_p, hl_p;
    {
        float v  = p[0];                                   // single coalesced LDG
        float l  = v * __log2f(v + EPS);                   // ONE log per pixel
        float vn = __shfl_down_sync(0xffffffffu, v, 1);
        float ln = __shfl_down_sync(0xffffffffu, l, 1);
        hv_p = v + vn;
        hl_p = l + ln;
        p += 256;
    }

    #pragma unroll 3
    for (int r = 0; r < RROWS; r++) {
        float v  = p[0];
        float l  = v * __log2f(v + EPS);
        float vn = __shfl_down_sync(0xffffffffu, v, 1);
        float ln = __shfl_down_sync(0xffffffffu, l, 1);
        float hv = v + vn;
        float hl = l + ln;

        float s   = hv_p + hv;                 // 2x2 window sum
        float sl  = hl_p + hl;                 // sum of w*lg2(w+eps)
        float S   = s + EPS;
        // ent = ln2 * (s*lg2(S) - sl) / S
        float ent = fmaf(s, __log2f(S), -sl) * fast_rcp(S) * LN2;
        if (storeOK) po[0] = ent;              // predicated, no branch

        hv_p = hv;
        hl_p = hl;
        p  += 256;
        po += 255;
    }
}

extern "C" void kernel_launch(void* const* d_in, const int* in_sizes, int n_in,
                              void* d_out, int out_size)
{
    const float* x = (const float*)d_in[0];
    float* out = (float*)d_out;

    // 9 warps x 31 output cols = 279 >= 255; 5 row-strips of 51 cover 255 rows.
    dim3 block(288);
    dim3 grid(1, 5, 512);
    entropy2x2_k5<<<grid, block>>>(x, out);
}